// round 7
// baseline (speedup 1.0000x reference)
#include <cuda_runtime.h>
#include <cuda_bf16.h>
#include <cstdint>

#define D 128
#define NMAX 100000
#define EMAX 1600000
#define SCAN_B 1024

// -------- scratch (static device allocations; no cudaMalloc allowed) --------
__device__ float         g_xw[(size_t)NMAX * D];     // x @ W   (51.2 MB)
__device__ __nv_bfloat16 g_xh[(size_t)NMAX * D];     // bf16 hi of x (25.6 MB)
__device__ __nv_bfloat16 g_xl[(size_t)NMAX * D];     // bf16 lo of x (25.6 MB)
__device__ __nv_bfloat16 g_wth[2 * D * D];           // W^T, Wl^T hi  [sel][n][k]
__device__ __nv_bfloat16 g_wtl[2 * D * D];           // W^T, Wl^T lo
__device__ float g_dinv[NMAX];
__device__ int   g_deg[NMAX];
__device__ int   g_row[NMAX];
__device__ int   g_cur[NMAX];
__device__ int   g_csr[EMAX];
__device__ int   g_bsum[(NMAX + SCAN_B - 1) / SCAN_B];
__device__ int   g_is64;

// ---------------------------------------------------------------------------
// Precompute: x -> bf16 hi/lo (8 elements per thread)
// ---------------------------------------------------------------------------
__global__ __launch_bounds__(256) void conv_x_kernel(
    const float* __restrict__ x, int total8)
{
    int i = blockIdx.x * blockDim.x + threadIdx.x;
    if (i >= total8) return;
    size_t base = (size_t)i * 8;
    float4 v0 = *(const float4*)&x[base];
    float4 v1 = *(const float4*)&x[base + 4];
    float f[8] = { v0.x, v0.y, v0.z, v0.w, v1.x, v1.y, v1.z, v1.w };
    __nv_bfloat16 h[8], l[8];
    #pragma unroll
    for (int j = 0; j < 8; j++) {
        h[j] = __float2bfloat16(f[j]);
        l[j] = __float2bfloat16(f[j] - __bfloat162float(h[j]));
    }
    *(uint4*)&g_xh[base] = *(const uint4*)h;
    *(uint4*)&g_xl[base] = *(const uint4*)l;
}

// Precompute: W,Wl -> transposed bf16 hi/lo.  out[sel][n][k] = in[k][n]
__global__ __launch_bounds__(256) void conv_w_kernel(
    const float* __restrict__ W, const float* __restrict__ Wl)
{
    int t = blockIdx.x * blockDim.x + threadIdx.x;   // 0..32767
    int sel = t >> 14;
    int idx = t & 16383;
    int n = idx >> 7;
    int k = idx & 127;
    const float* src = sel ? Wl : W;
    float f = src[k * D + n];
    __nv_bfloat16 h = __float2bfloat16(f);
    __nv_bfloat16 l = __float2bfloat16(f - __bfloat162float(h));
    g_wth[t] = h;
    g_wtl[t] = l;
}

// ---------------------------------------------------------------------------
// detect dtype (block 0) + deg init (all blocks)
// ---------------------------------------------------------------------------
__global__ void detect_init_kernel(const int* ei32, int n) {
    int i = blockIdx.x * blockDim.x + threadIdx.x;
    if (i < n) g_deg[i] = 1;   // self loop
    if (blockIdx.x == 0) {
        __shared__ int s_nonzero;
        if (threadIdx.x == 0) s_nonzero = 0;
        __syncthreads();
        int bad = 0;
        for (int k = threadIdx.x; k < 512; k += blockDim.x)
            if (ei32[2 * k + 1] != 0) bad = 1;
        if (bad) atomicOr(&s_nonzero, 1);
        __syncthreads();
        if (threadIdx.x == 0) g_is64 = s_nonzero ? 0 : 1;
    }
}

__global__ void deg_count(const void* ei, int E) {
    int e = blockIdx.x * blockDim.x + threadIdx.x;
    if (e >= E) return;
    int d;
    if (g_is64) d = (int)((const long long*)ei)[(size_t)E + e];
    else        d = ((const int*)ei)[(size_t)E + e];
    atomicAdd(&g_deg[d], 1);
}

// ---------------------------------------------------------------------------
// Exclusive scan of edge counts (deg-1) -> g_row; also computes dinv.
// ---------------------------------------------------------------------------
__global__ __launch_bounds__(SCAN_B) void scan1_kernel(int n) {
    __shared__ int sh[SCAN_B];
    int tid = threadIdx.x;
    int i = blockIdx.x * SCAN_B + tid;
    int dg = (i < n) ? g_deg[i] : 1;
    if (i < n) g_dinv[i] = rsqrtf((float)dg);
    int v = (i < n) ? (dg - 1) : 0;
    sh[tid] = v;
    __syncthreads();
    #pragma unroll
    for (int off = 1; off < SCAN_B; off <<= 1) {
        int t = (tid >= off) ? sh[tid - off] : 0;
        __syncthreads();
        sh[tid] += t;
        __syncthreads();
    }
    if (i < n) g_row[i] = sh[tid] - v;          // exclusive
    if (tid == SCAN_B - 1) g_bsum[blockIdx.x] = sh[tid];
}

__global__ __launch_bounds__(SCAN_B) void scan2_kernel(int nb) {
    __shared__ int sh[SCAN_B];
    int tid = threadIdx.x;
    int v = (tid < nb) ? g_bsum[tid] : 0;
    sh[tid] = v;
    __syncthreads();
    #pragma unroll
    for (int off = 1; off < SCAN_B; off <<= 1) {
        int t = (tid >= off) ? sh[tid - off] : 0;
        __syncthreads();
        sh[tid] += t;
        __syncthreads();
    }
    if (tid < nb) g_bsum[tid] = sh[tid] - v;    // exclusive
}

__global__ __launch_bounds__(SCAN_B) void scan3_kernel(int n) {
    int i = blockIdx.x * SCAN_B + threadIdx.x;
    if (i < n) {
        int r = g_row[i] + g_bsum[blockIdx.x];
        g_row[i] = r;
        g_cur[i] = r;
    }
}

__global__ __launch_bounds__(256) void fill_kernel(const void* ei, int E) {
    int e = blockIdx.x * blockDim.x + threadIdx.x;
    if (e >= E) return;
    int s, d;
    if (g_is64) {
        const long long* p = (const long long*)ei;
        s = (int)p[e];
        d = (int)p[(size_t)E + e];
    } else {
        const int* p = (const int*)ei;
        s = p[e];
        d = p[(size_t)E + e];
    }
    int pos = atomicAdd(&g_cur[d], 1);
    g_csr[pos] = s;
}

// ===========================================================================
// Lean GEMM: pre-converted bf16 operands, pure copy -> ldsm -> mma.
// grid.y = sel (0: W -> g_xw, 1: Wl -> out).
// ===========================================================================

#define SSTR 136
#define TILE_B (128 * SSTR * 2)
#define OFF_AHI 0
#define OFF_ALO (TILE_B)
#define OFF_BHI (2 * TILE_B)
#define OFF_BLO (3 * TILE_B)
#define GEMM_SMEM (4 * TILE_B)

__device__ __forceinline__ uint32_t smem_u32(const void* p) {
    uint32_t a;
    asm("{ .reg .u64 t; cvta.to.shared.u64 t, %1; cvt.u32.u64 %0, t; }"
        : "=r"(a) : "l"(p));
    return a;
}

__device__ __forceinline__ void ldsm_x4(uint32_t& r0, uint32_t& r1,
                                        uint32_t& r2, uint32_t& r3, uint32_t addr) {
    asm volatile("ldmatrix.sync.aligned.m8n8.x4.shared.b16 {%0,%1,%2,%3}, [%4];"
                 : "=r"(r0), "=r"(r1), "=r"(r2), "=r"(r3) : "r"(addr));
}

__device__ __forceinline__ void mma16816(float* c, const uint32_t* a,
                                         const uint32_t* b) {
    asm volatile(
        "mma.sync.aligned.m16n8k16.row.col.f32.bf16.bf16.f32 "
        "{%0,%1,%2,%3}, {%4,%5,%6,%7}, {%8,%9}, {%0,%1,%2,%3};"
        : "+f"(c[0]), "+f"(c[1]), "+f"(c[2]), "+f"(c[3])
        : "r"(a[0]), "r"(a[1]), "r"(a[2]), "r"(a[3]), "r"(b[0]), "r"(b[1]));
}

__global__ __launch_bounds__(256, 1) void gemm_mma_kernel(
    float* __restrict__ outh, int M)
{
    extern __shared__ char smem[];
    const uint32_t sb = smem_u32(smem);
    const int tid  = threadIdx.x;
    const int wid  = tid >> 5;
    const int lane = tid & 31;
    const int row0 = blockIdx.x * 128;
    const int sel  = blockIdx.y;
    float* Cout = sel ? outh : g_xw;

    // ---- copy A tiles (pre-converted bf16) ----
    {
        const int r  = tid >> 1;
        const int hf = tid & 1;
        const int grow = row0 + r;
        const bool ok = grow < M;
        const size_t gb = (size_t)grow * D + hf * 64;
        char* pHi = smem + OFF_AHI;
        char* pLo = smem + OFF_ALO;
        const uint32_t rb = (uint32_t)(r * SSTR + hf * 64) * 2;
        #pragma unroll
        for (int c8 = 0; c8 < 8; c8++) {
            uint4 vh = ok ? *(const uint4*)&g_xh[gb + c8 * 8] : make_uint4(0, 0, 0, 0);
            uint4 vl = ok ? *(const uint4*)&g_xl[gb + c8 * 8] : make_uint4(0, 0, 0, 0);
            *(uint4*)(pHi + rb + c8 * 16) = vh;
            *(uint4*)(pLo + rb + c8 * 16) = vl;
        }
    }

    // ---- copy B tiles (pre-converted transposed bf16) ----
    {
        const int n  = tid >> 1;
        const int kh = tid & 1;
        const size_t gb = (size_t)sel * D * D + (size_t)n * D + kh * 64;
        char* pHi = smem + OFF_BHI;
        char* pLo = smem + OFF_BLO;
        const uint32_t rb = (uint32_t)(n * SSTR + kh * 64) * 2;
        #pragma unroll
        for (int c8 = 0; c8 < 8; c8++) {
            uint4 vh = *(const uint4*)&g_wth[gb + c8 * 8];
            uint4 vl = *(const uint4*)&g_wtl[gb + c8 * 8];
            *(uint4*)(pHi + rb + c8 * 16) = vh;
            *(uint4*)(pLo + rb + c8 * 16) = vl;
        }
    }
    __syncthreads();

    const int mi = wid & 3;
    const int ni = wid >> 2;

    float c[2][8][4];
    #pragma unroll
    for (int mt = 0; mt < 2; mt++)
        #pragma unroll
        for (int nt = 0; nt < 8; nt++)
            #pragma unroll
            for (int q = 0; q < 4; q++) c[mt][nt][q] = 0.f;

    const int lmat = lane >> 3;
    const int lr   = lane & 7;
    const int rowc = ((lmat & 1) << 3) + lr;
    const int colc = (lmat >> 1) << 3;

    #pragma unroll
    for (int p = 0; p < 3; p++) {
        const uint32_t abase = sb + ((p < 2) ? OFF_AHI : OFF_ALO);
        const uint32_t bbase = sb + ((p == 1) ? OFF_BLO : OFF_BHI);
        const uint32_t a_rc = (uint32_t)((mi * 32 + rowc) * SSTR + colc) * 2;
        const uint32_t b_rc = (uint32_t)((ni * 64 + rowc) * SSTR + colc) * 2;

        #pragma unroll
        for (int k0 = 0; k0 < 8; k0++) {
            const uint32_t kb = (uint32_t)(k0 * 16) * 2;
            uint32_t afr[2][4];
            #pragma unroll
            for (int mt = 0; mt < 2; mt++)
                ldsm_x4(afr[mt][0], afr[mt][1], afr[mt][2], afr[mt][3],
                        abase + a_rc + kb + (uint32_t)(mt * 16 * SSTR) * 2);
            uint32_t bfr[8][2];
            #pragma unroll
            for (int nb = 0; nb < 4; nb++) {
                uint32_t r0, r1, r2, r3;
                ldsm_x4(r0, r1, r2, r3,
                        bbase + b_rc + kb + (uint32_t)(nb * 16 * SSTR) * 2);
                bfr[nb * 2][0]     = r0;  bfr[nb * 2][1]     = r2;
                bfr[nb * 2 + 1][0] = r1;  bfr[nb * 2 + 1][1] = r3;
            }
            #pragma unroll
            for (int mt = 0; mt < 2; mt++)
                #pragma unroll
                for (int nt = 0; nt < 8; nt++)
                    mma16816(c[mt][nt], afr[mt], bfr[nt]);
        }
    }

    const int g   = lane >> 2;
    const int tig = lane & 3;
    #pragma unroll
    for (int mt = 0; mt < 2; mt++) {
        #pragma unroll
        for (int nt = 0; nt < 8; nt++) {
            const int col  = ni * 64 + nt * 8 + tig * 2;
            const int row  = row0 + mi * 32 + mt * 16 + g;
            if (row < M)
                *(float2*)&Cout[(size_t)row * D + col] =
                    make_float2(c[mt][nt][0], c[mt][nt][1]);
            if (row + 8 < M)
                *(float2*)&Cout[(size_t)(row + 8) * D + col] =
                    make_float2(c[mt][nt][2], c[mt][nt][3]);
        }
    }
}

// ---------------------------------------------------------------------------
// Fused gather + self-loop + residual + LayerNorm. One warp per dst node.
// ---------------------------------------------------------------------------
__global__ __launch_bounds__(256) void gather_ln_kernel(
    float* __restrict__ out,
    const float* __restrict__ b,  const float* __restrict__ bl,
    const float* __restrict__ gamma, const float* __restrict__ beta, int n)
{
    int gtid = blockIdx.x * blockDim.x + threadIdx.x;
    int r    = gtid >> 5;
    int lane = gtid & 31;
    if (r >= n) return;

    const int start = g_row[r];
    const int cnt   = g_deg[r] - 1;
    const float di  = g_dinv[r];
    const int j = lane * 4;

    float ax = 0.f, ay = 0.f, az = 0.f, aw = 0.f;
    for (int base = 0; base < cnt; base += 32) {
        int m = cnt - base;
        int lim = m < 32 ? m : 32;
        int   idx = 0;
        float dsv = 0.f;
        if (lane < lim) {
            idx = __ldg(&g_csr[start + base + lane]);
            dsv = __ldg(&g_dinv[idx]);
        }
        int k = 0;
        for (; k + 4 <= lim; k += 4) {
            int   s0 = __shfl_sync(0xFFFFFFFFu, idx, k);
            int   s1 = __shfl_sync(0xFFFFFFFFu, idx, k + 1);
            int   s2 = __shfl_sync(0xFFFFFFFFu, idx, k + 2);
            int   s3 = __shfl_sync(0xFFFFFFFFu, idx, k + 3);
            float c0 = __shfl_sync(0xFFFFFFFFu, dsv, k);
            float c1 = __shfl_sync(0xFFFFFFFFu, dsv, k + 1);
            float c2 = __shfl_sync(0xFFFFFFFFu, dsv, k + 2);
            float c3 = __shfl_sync(0xFFFFFFFFu, dsv, k + 3);
            float4 v0 = *(const float4*)&g_xw[(size_t)s0 * D + j];
            float4 v1 = *(const float4*)&g_xw[(size_t)s1 * D + j];
            float4 v2 = *(const float4*)&g_xw[(size_t)s2 * D + j];
            float4 v3 = *(const float4*)&g_xw[(size_t)s3 * D + j];
            ax += v0.x * c0; ay += v0.y * c0; az += v0.z * c0; aw += v0.w * c0;
            ax += v1.x * c1; ay += v1.y * c1; az += v1.z * c1; aw += v1.w * c1;
            ax += v2.x * c2; ay += v2.y * c2; az += v2.z * c2; aw += v2.w * c2;
            ax += v3.x * c3; ay += v3.y * c3; az += v3.z * c3; aw += v3.w * c3;
        }
        for (; k < lim; k++) {
            int   s = __shfl_sync(0xFFFFFFFFu, idx, k);
            float c = __shfl_sync(0xFFFFFFFFu, dsv, k);
            float4 v = *(const float4*)&g_xw[(size_t)s * D + j];
            ax += v.x * c; ay += v.y * c; az += v.z * c; aw += v.w * c;
        }
    }

    const float sd = di * di;
    float4 xw  = *(const float4*)&g_xw[(size_t)r * D + j];
    float4 res = *(float4*)&out[(size_t)r * D + j];
    float4 b4  = *(const float4*)&b[j];
    float4 l4  = *(const float4*)&bl[j];
    float hx = ax * di + xw.x * sd + res.x + b4.x + l4.x;
    float hy = ay * di + xw.y * sd + res.y + b4.y + l4.y;
    float hz = az * di + xw.z * sd + res.z + b4.z + l4.z;
    float hw = aw * di + xw.w * sd + res.w + b4.w + l4.w;

    float s = hx + hy + hz + hw;
    #pragma unroll
    for (int o = 16; o > 0; o >>= 1) s += __shfl_xor_sync(0xFFFFFFFFu, s, o);
    float mu = s * (1.f / 128.f);

    float dx = hx - mu, dy = hy - mu, dz = hz - mu, dw = hw - mu;
    float sq = dx * dx + dy * dy + dz * dz + dw * dw;
    #pragma unroll
    for (int o = 16; o > 0; o >>= 1) sq += __shfl_xor_sync(0xFFFFFFFFu, sq, o);
    float rstd = rsqrtf(sq * (1.f / 128.f) + 1e-5f);

    float4 g4 = *(const float4*)&gamma[j];
    float4 e4 = *(const float4*)&beta[j];
    float4 o4;
    o4.x = dx * rstd * g4.x + e4.x;
    o4.y = dy * rstd * g4.y + e4.y;
    o4.z = dz * rstd * g4.z + e4.z;
    o4.w = dw * rstd * g4.w + e4.w;
    *(float4*)&out[(size_t)r * D + j] = o4;
}

// ---------------------------------------------------------------------------
static int s_init = 0;

extern "C" void kernel_launch(void* const* d_in, const int* in_sizes, int n_in,
                              void* d_out, int out_size)
{
    const float* x     = (const float*)d_in[0];
    const void*  ei    = d_in[1];
    const float* W     = (const float*)d_in[2];
    const float* b     = (const float*)d_in[3];
    const float* Wl    = (const float*)d_in[4];
    const float* bl    = (const float*)d_in[5];
    const float* gamma = (const float*)d_in[6];
    const float* beta  = (const float*)d_in[7];
    float* out = (float*)d_out;

    int N = in_sizes[0] / D;
    int E = in_sizes[1] / 2;
    int nb = (N + SCAN_B - 1) / SCAN_B;

    if (!s_init) {
        cudaFuncSetAttribute(gemm_mma_kernel,
                             cudaFuncAttributeMaxDynamicSharedMemorySize, GEMM_SMEM);
        s_init = 1;
    }

    // precompute bf16 operands
    int total8 = N * D / 8;
    conv_x_kernel<<<(total8 + 255) / 256, 256>>>(x, total8);
    conv_w_kernel<<<128, 256>>>(W, Wl);

    // CSR build
    detect_init_kernel<<<(N + 255) / 256, 256>>>((const int*)ei, N);
    deg_count<<<(E + 255) / 256, 256>>>(ei, E);
    scan1_kernel<<<nb, SCAN_B>>>(N);
    scan2_kernel<<<1, SCAN_B>>>(nb);
    scan3_kernel<<<nb, SCAN_B>>>(N);
    fill_kernel<<<(E + 255) / 256, 256>>>(ei, E);

    // GEMMs
    dim3 ggrid((N + 127) / 128, 2);
    gemm_mma_kernel<<<ggrid, 256, GEMM_SMEM>>>(out, N);

    // fused gather + LN
    long long lw = (long long)N * 32;
    gather_ln_kernel<<<(unsigned)((lw + 255) / 256), 256>>>(out, b, bl, gamma, beta, N);
}

// round 11
// speedup vs baseline: 1.0435x; 1.0435x over previous
#include <cuda_runtime.h>
#include <cuda_bf16.h>
#include <cstdint>

#define D 128
#define NMAX 100000
#define EMAX 1600000
#define SCAN_B 1024

// -------- scratch (static device allocations; no cudaMalloc allowed) --------
__device__ float g_xw[(size_t)NMAX * D];   // x @ W   (51.2 MB)
__device__ float g_dinv[NMAX];
__device__ int   g_deg[NMAX];
__device__ int   g_row[NMAX];
__device__ int   g_cur[NMAX];
__device__ int   g_csr[EMAX];
__device__ int   g_bsum[(NMAX + SCAN_B - 1) / SCAN_B];
__device__ int   g_is64;

// ---------------------------------------------------------------------------
__global__ void detect_init_kernel(const int* ei32, int n) {
    int i = blockIdx.x * blockDim.x + threadIdx.x;
    if (i < n) g_deg[i] = 1;   // self loop
    if (blockIdx.x == 0) {
        __shared__ int s_nonzero;
        if (threadIdx.x == 0) s_nonzero = 0;
        __syncthreads();
        int bad = 0;
        for (int k = threadIdx.x; k < 512; k += blockDim.x)
            if (ei32[2 * k + 1] != 0) bad = 1;
        if (bad) atomicOr(&s_nonzero, 1);
        __syncthreads();
        if (threadIdx.x == 0) g_is64 = s_nonzero ? 0 : 1;
    }
}

__global__ void deg_count(const void* ei, int E) {
    int e = blockIdx.x * blockDim.x + threadIdx.x;
    if (e >= E) return;
    int d;
    if (g_is64) d = (int)((const long long*)ei)[(size_t)E + e];
    else        d = ((const int*)ei)[(size_t)E + e];
    atomicAdd(&g_deg[d], 1);
}

__global__ __launch_bounds__(SCAN_B) void scan1_kernel(int n) {
    __shared__ int sh[SCAN_B];
    int tid = threadIdx.x;
    int i = blockIdx.x * SCAN_B + tid;
    int dg = (i < n) ? g_deg[i] : 1;
    if (i < n) g_dinv[i] = rsqrtf((float)dg);
    int v = (i < n) ? (dg - 1) : 0;
    sh[tid] = v;
    __syncthreads();
    #pragma unroll
    for (int off = 1; off < SCAN_B; off <<= 1) {
        int t = (tid >= off) ? sh[tid - off] : 0;
        __syncthreads();
        sh[tid] += t;
        __syncthreads();
    }
    if (i < n) g_row[i] = sh[tid] - v;
    if (tid == SCAN_B - 1) g_bsum[blockIdx.x] = sh[tid];
}

__global__ __launch_bounds__(SCAN_B) void scan2_kernel(int nb) {
    __shared__ int sh[SCAN_B];
    int tid = threadIdx.x;
    int v = (tid < nb) ? g_bsum[tid] : 0;
    sh[tid] = v;
    __syncthreads();
    #pragma unroll
    for (int off = 1; off < SCAN_B; off <<= 1) {
        int t = (tid >= off) ? sh[tid - off] : 0;
        __syncthreads();
        sh[tid] += t;
        __syncthreads();
    }
    if (tid < nb) g_bsum[tid] = sh[tid] - v;
}

__global__ __launch_bounds__(SCAN_B) void scan3_kernel(int n) {
    int i = blockIdx.x * SCAN_B + threadIdx.x;
    if (i < n) {
        int r = g_row[i] + g_bsum[blockIdx.x];
        g_row[i] = r;
        g_cur[i] = r;
    }
}

__global__ __launch_bounds__(256) void fill_kernel(const void* ei, int E) {
    int e = blockIdx.x * blockDim.x + threadIdx.x;
    if (e >= E) return;
    int s, d;
    if (g_is64) {
        const long long* p = (const long long*)ei;
        s = (int)p[e];
        d = (int)p[(size_t)E + e];
    } else {
        const int* p = (const int*)ei;
        s = p[e];
        d = p[(size_t)E + e];
    }
    int pos = atomicAdd(&g_cur[d], 1);
    g_csr[pos] = s;
}

// ===========================================================================
// Merged GEMM (mma.sync m16n8k16 bf16, fp32 accum, hi/lo split):
// one CTA computes BOTH  x@W -> g_xw  and  x@Wl -> out  for its 128-row tile.
// A stored [m][k] (regular ldsm); B stored [k][n] natural (ldsm .trans) so
// the weight conversion reads are coalesced float4s.
// ===========================================================================

#define SSTR 136
#define TILE_B (128 * SSTR * 2)           // 34816 bytes
#define OFF_AHI 0
#define OFF_ALO (TILE_B)
#define OFF_B0  (2 * TILE_B)              // B0HI, B0LO, B1HI, B1LO follow
#define GEMM_SMEM (6 * TILE_B)            // 208896 bytes

__device__ __forceinline__ uint32_t smem_u32(const void* p) {
    uint32_t a;
    asm("{ .reg .u64 t; cvta.to.shared.u64 t, %1; cvt.u32.u64 %0, t; }"
        : "=r"(a) : "l"(p));
    return a;
}

__device__ __forceinline__ void ldsm_x4(uint32_t& r0, uint32_t& r1,
                                        uint32_t& r2, uint32_t& r3, uint32_t addr) {
    asm volatile("ldmatrix.sync.aligned.m8n8.x4.shared.b16 {%0,%1,%2,%3}, [%4];"
                 : "=r"(r0), "=r"(r1), "=r"(r2), "=r"(r3) : "r"(addr));
}

__device__ __forceinline__ void ldsm_x4_t(uint32_t& r0, uint32_t& r1,
                                          uint32_t& r2, uint32_t& r3, uint32_t addr) {
    asm volatile("ldmatrix.sync.aligned.m8n8.x4.trans.shared.b16 {%0,%1,%2,%3}, [%4];"
                 : "=r"(r0), "=r"(r1), "=r"(r2), "=r"(r3) : "r"(addr));
}

__device__ __forceinline__ void mma16816(float* c, const uint32_t* a,
                                         const uint32_t* b) {
    asm volatile(
        "mma.sync.aligned.m16n8k16.row.col.f32.bf16.bf16.f32 "
        "{%0,%1,%2,%3}, {%4,%5,%6,%7}, {%8,%9}, {%0,%1,%2,%3};"
        : "+f"(c[0]), "+f"(c[1]), "+f"(c[2]), "+f"(c[3])
        : "r"(a[0]), "r"(a[1]), "r"(a[2]), "r"(a[3]), "r"(b[0]), "r"(b[1]));
}

__global__ __launch_bounds__(256, 1) void gemm_mma_kernel(
    const float* __restrict__ x,
    const float* __restrict__ W,
    const float* __restrict__ Wl,
    float* __restrict__ outh, int M)
{
    extern __shared__ char smem[];
    const uint32_t sb = smem_u32(smem);
    const int tid  = threadIdx.x;
    const int wid  = tid >> 5;
    const int lane = tid & 31;
    const int row0 = blockIdx.x * 128;

    // ---- A tile: convert x rows to hi/lo bf16, [m][k] layout ----
    {
        const int r  = tid >> 1;
        const int hf = tid & 1;
        const int grow = row0 + r;
        const bool ok = grow < M;
        const float* xr = x + (size_t)(ok ? grow : 0) * D + hf * 64;
        char* pHi = smem + OFF_AHI;
        char* pLo = smem + OFF_ALO;
        const uint32_t rb = (uint32_t)(r * SSTR + hf * 64) * 2;
        #pragma unroll
        for (int c4 = 0; c4 < 16; c4++) {
            float4 v = ok ? *(const float4*)&xr[c4 * 4]
                          : make_float4(0.f, 0.f, 0.f, 0.f);
            float f[4] = { v.x, v.y, v.z, v.w };
            __nv_bfloat16 h[4], l[4];
            #pragma unroll
            for (int j = 0; j < 4; j++) {
                h[j] = __float2bfloat16(f[j]);
                l[j] = __float2bfloat16(f[j] - __bfloat162float(h[j]));
            }
            *(uint2*)(pHi + rb + c4 * 8) = *(const uint2*)h;
            *(uint2*)(pLo + rb + c4 * 8) = *(const uint2*)l;
        }
    }

    // ---- B tiles: W and Wl, natural [k][n] layout, coalesced reads ----
    #pragma unroll
    for (int sel = 0; sel < 2; sel++) {
        const float* src = sel ? Wl : W;
        char* pHi = smem + OFF_B0 + sel * 2 * TILE_B;
        char* pLo = pHi + TILE_B;
        const int k  = tid >> 1;
        const int hf = tid & 1;
        const float* rp = src + (size_t)k * D + hf * 64;
        const uint32_t rb = (uint32_t)(k * SSTR + hf * 64) * 2;
        #pragma unroll
        for (int c4 = 0; c4 < 16; c4++) {
            float4 v = *(const float4*)&rp[c4 * 4];
            float f[4] = { v.x, v.y, v.z, v.w };
            __nv_bfloat16 h[4], l[4];
            #pragma unroll
            for (int j = 0; j < 4; j++) {
                h[j] = __float2bfloat16(f[j]);
                l[j] = __float2bfloat16(f[j] - __bfloat162float(h[j]));
            }
            *(uint2*)(pHi + rb + c4 * 8) = *(const uint2*)h;
            *(uint2*)(pLo + rb + c4 * 8) = *(const uint2*)l;
        }
    }
    __syncthreads();

    // ---- warp tiling: 4 warps along M x 2 along N; sel loop reuses A ----
    const int mi = wid & 3;
    const int ni = wid >> 2;

    const int lmat = lane >> 3;
    const int lr   = lane & 7;
    // A (regular ldsm): row-within-16 and k-half offsets
    const int a_rowc = ((lmat & 1) << 3) + lr;
    const int a_colc = (lmat >> 1) << 3;
    // B (trans ldsm on [k][n]): k-row-within-16 and n-offset
    const int b_krow = ((lmat >> 1) << 3) + lr;
    const int b_noff = (lmat & 1) << 3;

    #pragma unroll
    for (int sel = 0; sel < 2; sel++) {
        const uint32_t bsel = sb + OFF_B0 + sel * 2 * TILE_B;
        float c[2][8][4];
        #pragma unroll
        for (int mt = 0; mt < 2; mt++)
            #pragma unroll
            for (int nt = 0; nt < 8; nt++)
                #pragma unroll
                for (int q = 0; q < 4; q++) c[mt][nt][q] = 0.f;

        #pragma unroll
        for (int p = 0; p < 3; p++) {
            const uint32_t abase = sb + ((p < 2) ? OFF_AHI : OFF_ALO);
            const uint32_t bbase = bsel + ((p == 1) ? TILE_B : 0);
            const uint32_t a_rc = (uint32_t)((mi * 32 + a_rowc) * SSTR + a_colc) * 2;
            const uint32_t b_rc = (uint32_t)(b_krow * SSTR + ni * 64 + b_noff) * 2;

            #pragma unroll
            for (int k0 = 0; k0 < 8; k0++) {
                uint32_t afr[2][4];
                #pragma unroll
                for (int mt = 0; mt < 2; mt++)
                    ldsm_x4(afr[mt][0], afr[mt][1], afr[mt][2], afr[mt][3],
                            abase + a_rc + (uint32_t)(k0 * 16) * 2
                                  + (uint32_t)(mt * 16 * SSTR) * 2);
                uint32_t bfr[8][2];
                #pragma unroll
                for (int nb = 0; nb < 4; nb++) {
                    uint32_t r0, r1, r2, r3;
                    ldsm_x4_t(r0, r1, r2, r3,
                              bbase + b_rc + (uint32_t)(k0 * 16 * SSTR) * 2
                                    + (uint32_t)(nb * 16) * 2);
                    bfr[nb * 2][0]     = r0;  bfr[nb * 2][1]     = r2;
                    bfr[nb * 2 + 1][0] = r1;  bfr[nb * 2 + 1][1] = r3;
                }
                #pragma unroll
                for (int mt = 0; mt < 2; mt++)
                    #pragma unroll
                    for (int nt = 0; nt < 8; nt++)
                        mma16816(c[mt][nt], afr[mt], bfr[nt]);
            }
        }

        // ---- epilogue for this sel ----
        float* Cout = sel ? outh : g_xw;
        const int g   = lane >> 2;
        const int tig = lane & 3;
        #pragma unroll
        for (int mt = 0; mt < 2; mt++) {
            #pragma unroll
            for (int nt = 0; nt < 8; nt++) {
                const int col = ni * 64 + nt * 8 + tig * 2;
                const int row = row0 + mi * 32 + mt * 16 + g;
                if (row < M)
                    *(float2*)&Cout[(size_t)row * D + col] =
                        make_float2(c[mt][nt][0], c[mt][nt][1]);
                if (row + 8 < M)
                    *(float2*)&Cout[(size_t)(row + 8) * D + col] =
                        make_float2(c[mt][nt][2], c[mt][nt][3]);
            }
        }
    }
}

// ---------------------------------------------------------------------------
// Fused gather + self-loop + residual + LayerNorm. One warp per dst node.
// ---------------------------------------------------------------------------
__global__ __launch_bounds__(256) void gather_ln_kernel(
    float* __restrict__ out,
    const float* __restrict__ b,  const float* __restrict__ bl,
    const float* __restrict__ gamma, const float* __restrict__ beta, int n)
{
    int gtid = blockIdx.x * blockDim.x + threadIdx.x;
    int r    = gtid >> 5;
    int lane = gtid & 31;
    if (r >= n) return;

    const int start = g_row[r];
    const int cnt   = g_deg[r] - 1;
    const float di  = g_dinv[r];
    const int j = lane * 4;

    float ax = 0.f, ay = 0.f, az = 0.f, aw = 0.f;
    for (int base = 0; base < cnt; base += 32) {
        int m = cnt - base;
        int lim = m < 32 ? m : 32;
        int   idx = 0;
        float dsv = 0.f;
        if (lane < lim) {
            idx = __ldg(&g_csr[start + base + lane]);
            dsv = __ldg(&g_dinv[idx]);
        }
        int k = 0;
        for (; k + 4 <= lim; k += 4) {
            int   s0 = __shfl_sync(0xFFFFFFFFu, idx, k);
            int   s1 = __shfl_sync(0xFFFFFFFFu, idx, k + 1);
            int   s2 = __shfl_sync(0xFFFFFFFFu, idx, k + 2);
            int   s3 = __shfl_sync(0xFFFFFFFFu, idx, k + 3);
            float c0 = __shfl_sync(0xFFFFFFFFu, dsv, k);
            float c1 = __shfl_sync(0xFFFFFFFFu, dsv, k + 1);
            float c2 = __shfl_sync(0xFFFFFFFFu, dsv, k + 2);
            float c3 = __shfl_sync(0xFFFFFFFFu, dsv, k + 3);
            float4 v0 = *(const float4*)&g_xw[(size_t)s0 * D + j];
            float4 v1 = *(const float4*)&g_xw[(size_t)s1 * D + j];
            float4 v2 = *(const float4*)&g_xw[(size_t)s2 * D + j];
            float4 v3 = *(const float4*)&g_xw[(size_t)s3 * D + j];
            ax += v0.x * c0; ay += v0.y * c0; az += v0.z * c0; aw += v0.w * c0;
            ax += v1.x * c1; ay += v1.y * c1; az += v1.z * c1; aw += v1.w * c1;
            ax += v2.x * c2; ay += v2.y * c2; az += v2.z * c2; aw += v2.w * c2;
            ax += v3.x * c3; ay += v3.y * c3; az += v3.z * c3; aw += v3.w * c3;
        }
        for (; k < lim; k++) {
            int   s = __shfl_sync(0xFFFFFFFFu, idx, k);
            float c = __shfl_sync(0xFFFFFFFFu, dsv, k);
            float4 v = *(const float4*)&g_xw[(size_t)s * D + j];
            ax += v.x * c; ay += v.y * c; az += v.z * c; aw += v.w * c;
        }
    }

    const float sd = di * di;
    float4 xw  = *(const float4*)&g_xw[(size_t)r * D + j];
    float4 res = *(float4*)&out[(size_t)r * D + j];
    float4 b4  = *(const float4*)&b[j];
    float4 l4  = *(const float4*)&bl[j];
    float hx = ax * di + xw.x * sd + res.x + b4.x + l4.x;
    float hy = ay * di + xw.y * sd + res.y + b4.y + l4.y;
    float hz = az * di + xw.z * sd + res.z + b4.z + l4.z;
    float hw = aw * di + xw.w * sd + res.w + b4.w + l4.w;

    float s = hx + hy + hz + hw;
    #pragma unroll
    for (int o = 16; o > 0; o >>= 1) s += __shfl_xor_sync(0xFFFFFFFFu, s, o);
    float mu = s * (1.f / 128.f);

    float dx = hx - mu, dy = hy - mu, dz = hz - mu, dw = hw - mu;
    float sq = dx * dx + dy * dy + dz * dz + dw * dw;
    #pragma unroll
    for (int o = 16; o > 0; o >>= 1) sq += __shfl_xor_sync(0xFFFFFFFFu, sq, o);
    float rstd = rsqrtf(sq * (1.f / 128.f) + 1e-5f);

    float4 g4 = *(const float4*)&gamma[j];
    float4 e4 = *(const float4*)&beta[j];
    float4 o4;
    o4.x = dx * rstd * g4.x + e4.x;
    o4.y = dy * rstd * g4.y + e4.y;
    o4.z = dz * rstd * g4.z + e4.z;
    o4.w = dw * rstd * g4.w + e4.w;
    *(float4*)&out[(size_t)r * D + j] = o4;
}

// ---------------------------------------------------------------------------
static int s_init = 0;

extern "C" void kernel_launch(void* const* d_in, const int* in_sizes, int n_in,
                              void* d_out, int out_size)
{
    const float* x     = (const float*)d_in[0];
    const void*  ei    = d_in[1];
    const float* W     = (const float*)d_in[2];
    const float* b     = (const float*)d_in[3];
    const float* Wl    = (const float*)d_in[4];
    const float* bl    = (const float*)d_in[5];
    const float* gamma = (const float*)d_in[6];
    const float* beta  = (const float*)d_in[7];
    float* out = (float*)d_out;

    int N = in_sizes[0] / D;
    int E = in_sizes[1] / 2;
    int nb = (N + SCAN_B - 1) / SCAN_B;

    if (!s_init) {
        cudaFuncSetAttribute(gemm_mma_kernel,
                             cudaFuncAttributeMaxDynamicSharedMemorySize, GEMM_SMEM);
        s_init = 1;
    }

    // CSR build
    detect_init_kernel<<<(N + 255) / 256, 256>>>((const int*)ei, N);
    deg_count<<<(E + 255) / 256, 256>>>(ei, E);
    scan1_kernel<<<nb, SCAN_B>>>(N);
    scan2_kernel<<<1, SCAN_B>>>(nb);
    scan3_kernel<<<nb, SCAN_B>>>(N);
    fill_kernel<<<(E + 255) / 256, 256>>>(ei, E);

    // merged GEMM (both W and Wl per CTA)
    gemm_mma_kernel<<<(N + 127) / 128, 256, GEMM_SMEM>>>(x, W, Wl, out, N);

    // fused gather + LN
    long long lw = (long long)N * 32;
    gather_ln_kernel<<<(unsigned)((lw + 255) / 256), 256>>>(out, b, bl, gamma, beta, N);
}

// round 12
// speedup vs baseline: 1.1790x; 1.1298x over previous
#include <cuda_runtime.h>
#include <cuda_bf16.h>
#include <cuda_fp16.h>
#include <cstdint>

#define D 128
#define NMAX 100000
#define EMAX 1600000
#define SCAN_B 1024

// -------- scratch (static device allocations; no cudaMalloc allowed) --------
__device__ __half g_xwh[(size_t)NMAX * D]; // (x@W)*dinv[row], fp16 (25.6 MB)
__device__ float g_dinv[NMAX];
__device__ int   g_deg[NMAX];
__device__ int   g_row[NMAX];
__device__ int   g_cur[NMAX];
__device__ int   g_csr[EMAX];
__device__ int   g_bsum[(NMAX + SCAN_B - 1) / SCAN_B];
__device__ int   g_is64;

// ---------------------------------------------------------------------------
__global__ void detect_init_kernel(const int* ei32, int n) {
    int i = blockIdx.x * blockDim.x + threadIdx.x;
    if (i < n) g_deg[i] = 1;   // self loop
    if (blockIdx.x == 0) {
        __shared__ int s_nonzero;
        if (threadIdx.x == 0) s_nonzero = 0;
        __syncthreads();
        int bad = 0;
        for (int k = threadIdx.x; k < 512; k += blockDim.x)
            if (ei32[2 * k + 1] != 0) bad = 1;
        if (bad) atomicOr(&s_nonzero, 1);
        __syncthreads();
        if (threadIdx.x == 0) g_is64 = s_nonzero ? 0 : 1;
    }
}

__global__ void deg_count(const void* ei, int E) {
    int e = blockIdx.x * blockDim.x + threadIdx.x;
    if (e >= E) return;
    int d;
    if (g_is64) d = (int)((const long long*)ei)[(size_t)E + e];
    else        d = ((const int*)ei)[(size_t)E + e];
    atomicAdd(&g_deg[d], 1);
}

__global__ __launch_bounds__(SCAN_B) void scan1_kernel(int n) {
    __shared__ int sh[SCAN_B];
    int tid = threadIdx.x;
    int i = blockIdx.x * SCAN_B + tid;
    int dg = (i < n) ? g_deg[i] : 1;
    if (i < n) g_dinv[i] = rsqrtf((float)dg);
    int v = (i < n) ? (dg - 1) : 0;
    sh[tid] = v;
    __syncthreads();
    #pragma unroll
    for (int off = 1; off < SCAN_B; off <<= 1) {
        int t = (tid >= off) ? sh[tid - off] : 0;
        __syncthreads();
        sh[tid] += t;
        __syncthreads();
    }
    if (i < n) g_row[i] = sh[tid] - v;
    if (tid == SCAN_B - 1) g_bsum[blockIdx.x] = sh[tid];
}

__global__ __launch_bounds__(SCAN_B) void scan2_kernel(int nb) {
    __shared__ int sh[SCAN_B];
    int tid = threadIdx.x;
    int v = (tid < nb) ? g_bsum[tid] : 0;
    sh[tid] = v;
    __syncthreads();
    #pragma unroll
    for (int off = 1; off < SCAN_B; off <<= 1) {
        int t = (tid >= off) ? sh[tid - off] : 0;
        __syncthreads();
        sh[tid] += t;
        __syncthreads();
    }
    if (tid < nb) g_bsum[tid] = sh[tid] - v;
}

__global__ __launch_bounds__(SCAN_B) void scan3_kernel(int n) {
    int i = blockIdx.x * SCAN_B + threadIdx.x;
    if (i < n) {
        int r = g_row[i] + g_bsum[blockIdx.x];
        g_row[i] = r;
        g_cur[i] = r;
    }
}

__global__ __launch_bounds__(256) void fill_kernel(const void* ei, int E) {
    int e = blockIdx.x * blockDim.x + threadIdx.x;
    if (e >= E) return;
    int s, d;
    if (g_is64) {
        const long long* p = (const long long*)ei;
        s = (int)p[e];
        d = (int)p[(size_t)E + e];
    } else {
        const int* p = (const int*)ei;
        s = p[e];
        d = p[(size_t)E + e];
    }
    int pos = atomicAdd(&g_cur[d], 1);
    g_csr[pos] = s;
}

// ===========================================================================
// Merged GEMM (mma.sync m16n8k16 bf16, fp32 accum, hi/lo split).
// sel 0: (x@W)*dinv[row] -> g_xwh (fp16);  sel 1: x@Wl -> out (fp32).
// ===========================================================================

#define SSTR 136
#define TILE_B (128 * SSTR * 2)
#define OFF_AHI 0
#define OFF_ALO (TILE_B)
#define OFF_B0  (2 * TILE_B)
#define GEMM_SMEM (6 * TILE_B)

__device__ __forceinline__ uint32_t smem_u32(const void* p) {
    uint32_t a;
    asm("{ .reg .u64 t; cvta.to.shared.u64 t, %1; cvt.u32.u64 %0, t; }"
        : "=r"(a) : "l"(p));
    return a;
}

__device__ __forceinline__ void ldsm_x4(uint32_t& r0, uint32_t& r1,
                                        uint32_t& r2, uint32_t& r3, uint32_t addr) {
    asm volatile("ldmatrix.sync.aligned.m8n8.x4.shared.b16 {%0,%1,%2,%3}, [%4];"
                 : "=r"(r0), "=r"(r1), "=r"(r2), "=r"(r3) : "r"(addr));
}

__device__ __forceinline__ void ldsm_x4_t(uint32_t& r0, uint32_t& r1,
                                          uint32_t& r2, uint32_t& r3, uint32_t addr) {
    asm volatile("ldmatrix.sync.aligned.m8n8.x4.trans.shared.b16 {%0,%1,%2,%3}, [%4];"
                 : "=r"(r0), "=r"(r1), "=r"(r2), "=r"(r3) : "r"(addr));
}

__device__ __forceinline__ void mma16816(float* c, const uint32_t* a,
                                         const uint32_t* b) {
    asm volatile(
        "mma.sync.aligned.m16n8k16.row.col.f32.bf16.bf16.f32 "
        "{%0,%1,%2,%3}, {%4,%5,%6,%7}, {%8,%9}, {%0,%1,%2,%3};"
        : "+f"(c[0]), "+f"(c[1]), "+f"(c[2]), "+f"(c[3])
        : "r"(a[0]), "r"(a[1]), "r"(a[2]), "r"(a[3]), "r"(b[0]), "r"(b[1]));
}

__global__ __launch_bounds__(256, 1) void gemm_mma_kernel(
    const float* __restrict__ x,
    const float* __restrict__ W,
    const float* __restrict__ Wl,
    float* __restrict__ outh, int M)
{
    extern __shared__ char smem[];
    const uint32_t sb = smem_u32(smem);
    const int tid  = threadIdx.x;
    const int wid  = tid >> 5;
    const int lane = tid & 31;
    const int row0 = blockIdx.x * 128;

    // ---- A tile: convert x rows to hi/lo bf16, [m][k] layout ----
    {
        const int r  = tid >> 1;
        const int hf = tid & 1;
        const int grow = row0 + r;
        const bool ok = grow < M;
        const float* xr = x + (size_t)(ok ? grow : 0) * D + hf * 64;
        char* pHi = smem + OFF_AHI;
        char* pLo = smem + OFF_ALO;
        const uint32_t rb = (uint32_t)(r * SSTR + hf * 64) * 2;
        #pragma unroll
        for (int c4 = 0; c4 < 16; c4++) {
            float4 v = ok ? *(const float4*)&xr[c4 * 4]
                          : make_float4(0.f, 0.f, 0.f, 0.f);
            float f[4] = { v.x, v.y, v.z, v.w };
            __nv_bfloat16 h[4], l[4];
            #pragma unroll
            for (int j = 0; j < 4; j++) {
                h[j] = __float2bfloat16(f[j]);
                l[j] = __float2bfloat16(f[j] - __bfloat162float(h[j]));
            }
            *(uint2*)(pHi + rb + c4 * 8) = *(const uint2*)h;
            *(uint2*)(pLo + rb + c4 * 8) = *(const uint2*)l;
        }
    }

    // ---- B tiles: W and Wl, natural [k][n] layout, coalesced reads ----
    #pragma unroll
    for (int sel = 0; sel < 2; sel++) {
        const float* src = sel ? Wl : W;
        char* pHi = smem + OFF_B0 + sel * 2 * TILE_B;
        char* pLo = pHi + TILE_B;
        const int k  = tid >> 1;
        const int hf = tid & 1;
        const float* rp = src + (size_t)k * D + hf * 64;
        const uint32_t rb = (uint32_t)(k * SSTR + hf * 64) * 2;
        #pragma unroll
        for (int c4 = 0; c4 < 16; c4++) {
            float4 v = *(const float4*)&rp[c4 * 4];
            float f[4] = { v.x, v.y, v.z, v.w };
            __nv_bfloat16 h[4], l[4];
            #pragma unroll
            for (int j = 0; j < 4; j++) {
                h[j] = __float2bfloat16(f[j]);
                l[j] = __float2bfloat16(f[j] - __bfloat162float(h[j]));
            }
            *(uint2*)(pHi + rb + c4 * 8) = *(const uint2*)h;
            *(uint2*)(pLo + rb + c4 * 8) = *(const uint2*)l;
        }
    }
    __syncthreads();

    const int mi = wid & 3;
    const int ni = wid >> 2;

    const int lmat = lane >> 3;
    const int lr   = lane & 7;
    const int a_rowc = ((lmat & 1) << 3) + lr;
    const int a_colc = (lmat >> 1) << 3;
    const int b_krow = ((lmat >> 1) << 3) + lr;
    const int b_noff = (lmat & 1) << 3;

    #pragma unroll
    for (int sel = 0; sel < 2; sel++) {
        const uint32_t bsel = sb + OFF_B0 + sel * 2 * TILE_B;
        float c[2][8][4];
        #pragma unroll
        for (int mt = 0; mt < 2; mt++)
            #pragma unroll
            for (int nt = 0; nt < 8; nt++)
                #pragma unroll
                for (int q = 0; q < 4; q++) c[mt][nt][q] = 0.f;

        #pragma unroll
        for (int p = 0; p < 3; p++) {
            const uint32_t abase = sb + ((p < 2) ? OFF_AHI : OFF_ALO);
            const uint32_t bbase = bsel + ((p == 1) ? TILE_B : 0);
            const uint32_t a_rc = (uint32_t)((mi * 32 + a_rowc) * SSTR + a_colc) * 2;
            const uint32_t b_rc = (uint32_t)(b_krow * SSTR + ni * 64 + b_noff) * 2;

            #pragma unroll
            for (int k0 = 0; k0 < 8; k0++) {
                uint32_t afr[2][4];
                #pragma unroll
                for (int mt = 0; mt < 2; mt++)
                    ldsm_x4(afr[mt][0], afr[mt][1], afr[mt][2], afr[mt][3],
                            abase + a_rc + (uint32_t)(k0 * 16) * 2
                                  + (uint32_t)(mt * 16 * SSTR) * 2);
                uint32_t bfr[8][2];
                #pragma unroll
                for (int nb = 0; nb < 4; nb++) {
                    uint32_t r0, r1, r2, r3;
                    ldsm_x4_t(r0, r1, r2, r3,
                              bbase + b_rc + (uint32_t)(k0 * 16 * SSTR) * 2
                                    + (uint32_t)(nb * 16) * 2);
                    bfr[nb * 2][0]     = r0;  bfr[nb * 2][1]     = r2;
                    bfr[nb * 2 + 1][0] = r1;  bfr[nb * 2 + 1][1] = r3;
                }
                #pragma unroll
                for (int mt = 0; mt < 2; mt++)
                    #pragma unroll
                    for (int nt = 0; nt < 8; nt++)
                        mma16816(c[mt][nt], afr[mt], bfr[nt]);
            }
        }

        // ---- epilogue ----
        const int g   = lane >> 2;
        const int tig = lane & 3;
        if (sel == 0) {
            // store (x@W)*dinv[row] as fp16
            #pragma unroll
            for (int mt = 0; mt < 2; mt++) {
                const int row = row0 + mi * 32 + mt * 16 + g;
                float di0 = (row < M)     ? g_dinv[row]     : 0.f;
                float di1 = (row + 8 < M) ? g_dinv[row + 8] : 0.f;
                #pragma unroll
                for (int nt = 0; nt < 8; nt++) {
                    const int col = ni * 64 + nt * 8 + tig * 2;
                    if (row < M)
                        *(__half2*)&g_xwh[(size_t)row * D + col] =
                            __floats2half2_rn(c[mt][nt][0] * di0, c[mt][nt][1] * di0);
                    if (row + 8 < M)
                        *(__half2*)&g_xwh[(size_t)(row + 8) * D + col] =
                            __floats2half2_rn(c[mt][nt][2] * di1, c[mt][nt][3] * di1);
                }
            }
        } else {
            #pragma unroll
            for (int mt = 0; mt < 2; mt++) {
                #pragma unroll
                for (int nt = 0; nt < 8; nt++) {
                    const int col = ni * 64 + nt * 8 + tig * 2;
                    const int row = row0 + mi * 32 + mt * 16 + g;
                    if (row < M)
                        *(float2*)&outh[(size_t)row * D + col] =
                            make_float2(c[mt][nt][0], c[mt][nt][1]);
                    if (row + 8 < M)
                        *(float2*)&outh[(size_t)(row + 8) * D + col] =
                            make_float2(c[mt][nt][2], c[mt][nt][3]);
                }
            }
        }
    }
}

// ---------------------------------------------------------------------------
// Fused gather + self-loop + residual + LayerNorm. One warp per dst node.
// g_xwh rows are pre-scaled by dinv[src]: agg = (sum + self) * dinv[r].
// ---------------------------------------------------------------------------
__global__ __launch_bounds__(256) void gather_ln_kernel(
    float* __restrict__ out,
    const float* __restrict__ b,  const float* __restrict__ bl,
    const float* __restrict__ gamma, const float* __restrict__ beta, int n)
{
    int gtid = blockIdx.x * blockDim.x + threadIdx.x;
    int r    = gtid >> 5;
    int lane = gtid & 31;
    if (r >= n) return;

    const int start = g_row[r];
    const int cnt   = g_deg[r] - 1;
    const float di  = g_dinv[r];
    const int j = lane * 4;

    float ax = 0.f, ay = 0.f, az = 0.f, aw = 0.f;
    for (int base = 0; base < cnt; base += 32) {
        int m = cnt - base;
        int lim = m < 32 ? m : 32;
        int idx = 0;
        if (lane < lim) idx = __ldg(&g_csr[start + base + lane]);
        int k = 0;
        for (; k + 4 <= lim; k += 4) {
            int s0 = __shfl_sync(0xFFFFFFFFu, idx, k);
            int s1 = __shfl_sync(0xFFFFFFFFu, idx, k + 1);
            int s2 = __shfl_sync(0xFFFFFFFFu, idx, k + 2);
            int s3 = __shfl_sync(0xFFFFFFFFu, idx, k + 3);
            uint2 u0 = *(const uint2*)&g_xwh[(size_t)s0 * D + j];
            uint2 u1 = *(const uint2*)&g_xwh[(size_t)s1 * D + j];
            uint2 u2 = *(const uint2*)&g_xwh[(size_t)s2 * D + j];
            uint2 u3 = *(const uint2*)&g_xwh[(size_t)s3 * D + j];
            float2 p0a = __half22float2(*(__half2*)&u0.x), p0b = __half22float2(*(__half2*)&u0.y);
            float2 p1a = __half22float2(*(__half2*)&u1.x), p1b = __half22float2(*(__half2*)&u1.y);
            float2 p2a = __half22float2(*(__half2*)&u2.x), p2b = __half22float2(*(__half2*)&u2.y);
            float2 p3a = __half22float2(*(__half2*)&u3.x), p3b = __half22float2(*(__half2*)&u3.y);
            ax += p0a.x + p1a.x + p2a.x + p3a.x;
            ay += p0a.y + p1a.y + p2a.y + p3a.y;
            az += p0b.x + p1b.x + p2b.x + p3b.x;
            aw += p0b.y + p1b.y + p2b.y + p3b.y;
        }
        for (; k < lim; k++) {
            int s = __shfl_sync(0xFFFFFFFFu, idx, k);
            uint2 u = *(const uint2*)&g_xwh[(size_t)s * D + j];
            float2 pa = __half22float2(*(__half2*)&u.x);
            float2 pb = __half22float2(*(__half2*)&u.y);
            ax += pa.x; ay += pa.y; az += pb.x; aw += pb.y;
        }
    }

    // self loop: stored value = xw[r]*di, so adding it into the sum and
    // multiplying by di gives xw[r]*di^2 + agg*di, exactly the GCN terms.
    {
        uint2 u = *(const uint2*)&g_xwh[(size_t)r * D + j];
        float2 pa = __half22float2(*(__half2*)&u.x);
        float2 pb = __half22float2(*(__half2*)&u.y);
        ax += pa.x; ay += pa.y; az += pb.x; aw += pb.y;
    }

    float4 res = *(float4*)&out[(size_t)r * D + j];
    float4 b4  = *(const float4*)&b[j];
    float4 l4  = *(const float4*)&bl[j];
    float hx = ax * di + res.x + b4.x + l4.x;
    float hy = ay * di + res.y + b4.y + l4.y;
    float hz = az * di + res.z + b4.z + l4.z;
    float hw = aw * di + res.w + b4.w + l4.w;

    float s = hx + hy + hz + hw;
    #pragma unroll
    for (int o = 16; o > 0; o >>= 1) s += __shfl_xor_sync(0xFFFFFFFFu, s, o);
    float mu = s * (1.f / 128.f);

    float dx = hx - mu, dy = hy - mu, dz = hz - mu, dw = hw - mu;
    float sq = dx * dx + dy * dy + dz * dz + dw * dw;
    #pragma unroll
    for (int o = 16; o > 0; o >>= 1) sq += __shfl_xor_sync(0xFFFFFFFFu, sq, o);
    float rstd = rsqrtf(sq * (1.f / 128.f) + 1e-5f);

    float4 g4 = *(const float4*)&gamma[j];
    float4 e4 = *(const float4*)&beta[j];
    float4 o4;
    o4.x = dx * rstd * g4.x + e4.x;
    o4.y = dy * rstd * g4.y + e4.y;
    o4.z = dz * rstd * g4.z + e4.z;
    o4.w = dw * rstd * g4.w + e4.w;
    *(float4*)&out[(size_t)r * D + j] = o4;
}

// ---------------------------------------------------------------------------
static int s_init = 0;

extern "C" void kernel_launch(void* const* d_in, const int* in_sizes, int n_in,
                              void* d_out, int out_size)
{
    const float* x     = (const float*)d_in[0];
    const void*  ei    = d_in[1];
    const float* W     = (const float*)d_in[2];
    const float* b     = (const float*)d_in[3];
    const float* Wl    = (const float*)d_in[4];
    const float* bl    = (const float*)d_in[5];
    const float* gamma = (const float*)d_in[6];
    const float* beta  = (const float*)d_in[7];
    float* out = (float*)d_out;

    int N = in_sizes[0] / D;
    int E = in_sizes[1] / 2;
    int nb = (N + SCAN_B - 1) / SCAN_B;

    if (!s_init) {
        cudaFuncSetAttribute(gemm_mma_kernel,
                             cudaFuncAttributeMaxDynamicSharedMemorySize, GEMM_SMEM);
        s_init = 1;
    }

    // CSR build (dinv ready after scan1 — required by the GEMM epilogue)
    detect_init_kernel<<<(N + 255) / 256, 256>>>((const int*)ei, N);
    deg_count<<<(E + 255) / 256, 256>>>(ei, E);
    scan1_kernel<<<nb, SCAN_B>>>(N);
    scan2_kernel<<<1, SCAN_B>>>(nb);
    scan3_kernel<<<nb, SCAN_B>>>(N);
    fill_kernel<<<(E + 255) / 256, 256>>>(ei, E);

    // merged GEMM (writes fp16 pre-scaled gather operand + fp32 residual)
    gemm_mma_kernel<<<(N + 127) / 128, 256, GEMM_SMEM>>>(x, W, Wl, out, N);

    // fused gather + LN
    long long lw = (long long)N * 32;
    gather_ln_kernel<<<(unsigned)((lw + 255) / 256), 256>>>(out, b, bl, gamma, beta, N);
}